// round 1
// baseline (speedup 1.0000x reference)
#include <cuda_runtime.h>
#include <cstdint>

#define B_TOTAL 16384
#define K_DIM   4096
#define NDOTS   32
#define F_EPS   1.1920929e-07f

// scratch (no allocations allowed)
__device__ float g_H[B_TOTAL * NDOTS];   // raw dots (unscaled)
__device__ float g_SS[B_TOTAL];          // sum of squares
__device__ float g_C[B_TOTAL * 16];      // per-row 4x4 combination matrix

__device__ __forceinline__ void ffma2(unsigned long long &acc,
                                      unsigned long long a,
                                      unsigned long long b) {
    asm("fma.rn.f32x2 %0, %1, %2, %0;" : "+l"(acc) : "l"(a), "l"(b));
}
__device__ __forceinline__ float hsum2(unsigned long long v) {
    return __uint_as_float((unsigned)(v & 0xffffffffull)) +
           __uint_as_float((unsigned)(v >> 32));
}

// ---------------------------------------------------------------------------
// K1: raw dots (32 per row) + sum of squares.
// Grid 1024, block 512. CTA tile: 16 rows x 32 dots.
// Warp tile: 4 rows x 8 dots, k-dimension split across lanes (lane owns
// k = 4*lane + 128*t). All loads coalesced; smem reads conflict-free.
// ---------------------------------------------------------------------------
__global__ __launch_bounds__(512, 1)
void k1_dots(const float* __restrict__ x,
             const float* __restrict__ Wri,
             const float* __restrict__ Wwo,
             const float* __restrict__ Wsm) {
    __shared__ float xs[16][128];
    __shared__ float ws[32][128];

    const int tid  = threadIdx.x;
    const int warp = tid >> 5;
    const int lane = tid & 31;
    const int rg   = warp & 3;   // row group (4 rows)
    const int dg   = warp >> 2;  // dot group (8 dots)
    const int row0 = blockIdx.x * 16;

    unsigned long long acc[4][8];
#pragma unroll
    for (int i = 0; i < 4; i++)
#pragma unroll
        for (int j = 0; j < 8; j++) acc[i][j] = 0ull;
    unsigned long long ss[4] = {0ull, 0ull, 0ull, 0ull};

    const int lrow = tid >> 5;   // x-load row (0..15): one warp per row
    const int lkq  = tid & 31;

    for (int t = 0; t < 32; t++) {
        const int k0 = t * 128;
        // cooperative x tile load: 16 rows x 128 cols, 1 float4/thread
        *(float4*)(&xs[lrow][lkq * 4]) =
            *(const float4*)(x + (row0 + lrow) * K_DIM + k0 + lkq * 4);
        // cooperative W tile load: 32 rows x 128 cols, 2 float4/thread
#pragma unroll
        for (int l = 0; l < 2; l++) {
            const int fidx = tid + l * 512;
            const int d  = fidx >> 5;
            const int kq = fidx & 31;
            const float* wrow = (d < 8)  ? (Wri + d * K_DIM)
                              : (d < 16) ? (Wwo + (d - 8) * K_DIM)
                                         : (Wsm + (d - 16) * K_DIM);
            *(float4*)(&ws[d][kq * 4]) = *(const float4*)(wrow + k0 + kq * 4);
        }
        __syncthreads();

        unsigned long long xa[4], xb[4];
#pragma unroll
        for (int i = 0; i < 4; i++) {
            const ulonglong2 v = *(const ulonglong2*)(&xs[rg * 4 + i][lane * 4]);
            xa[i] = v.x; xb[i] = v.y;
        }
        if (dg == 0) {
#pragma unroll
            for (int i = 0; i < 4; i++) {
                ffma2(ss[i], xa[i], xa[i]);
                ffma2(ss[i], xb[i], xb[i]);
            }
        }
#pragma unroll
        for (int j = 0; j < 8; j++) {
            const ulonglong2 w = *(const ulonglong2*)(&ws[dg * 8 + j][lane * 4]);
#pragma unroll
            for (int i = 0; i < 4; i++) {
                ffma2(acc[i][j], xa[i], w.x);
                ffma2(acc[i][j], xb[i], w.y);
            }
        }
        __syncthreads();
    }

    // cross-lane reduction + writes
#pragma unroll
    for (int i = 0; i < 4; i++) {
#pragma unroll
        for (int j = 0; j < 8; j++) {
            float v = hsum2(acc[i][j]);
#pragma unroll
            for (int off = 16; off; off >>= 1)
                v += __shfl_xor_sync(0xffffffffu, v, off);
            if (lane == i * 8 + j)
                g_H[(row0 + rg * 4 + i) * NDOTS + dg * 8 + j] = v;
        }
    }
    if (dg == 0) {
#pragma unroll
        for (int i = 0; i < 4; i++) {
            float v = hsum2(ss[i]);
#pragma unroll
            for (int off = 16; off; off >>= 1)
                v += __shfl_xor_sync(0xffffffffu, v, off);
            if (lane == 0) g_SS[row0 + rg * 4 + i] = v;
        }
    }
}

// ---------------------------------------------------------------------------
// K2: per-row gate math. sigmoids + 20-iter Sinkhorn on 4x4 -> C (4x4).
// One thread per row.
// ---------------------------------------------------------------------------
__global__ __launch_bounds__(256)
void k2_gates(const float* __restrict__ read_in,  const float* __restrict__ a_ri,
              const float* __restrict__ write_out, const float* __restrict__ a_wo,
              const float* __restrict__ stream_mixing, const float* __restrict__ a_sm) {
    const int b = blockIdx.x * blockDim.x + threadIdx.x;
    if (b >= B_TOTAL) return;

    const float s = rsqrtf(g_SS[b] * (1.0f / (float)K_DIM) + F_EPS);
    float h[32];
#pragma unroll
    for (int d = 0; d < 32; d++) h[d] = g_H[b * NDOTS + d] * s;

    const float ari = a_ri[0], awo = a_wo[0], asmix = a_sm[0];

    float riT[2][4], wo[4][2], p[4][4];
#pragma unroll
    for (int n = 0; n < 4; n++)
#pragma unroll
        for (int m = 0; m < 2; m++) {
            const float hri = ari * h[n * 2 + m] + read_in[n * 2 + m];
            riT[m][n] = 1.0f / (1.0f + expf(-hri));
            const float hwo = awo * h[8 + n * 2 + m] + write_out[n * 2 + m];
            wo[n][m] = 2.0f / (1.0f + expf(-hwo));
        }
#pragma unroll
    for (int i = 0; i < 4; i++)
#pragma unroll
        for (int j = 0; j < 4; j++)
            p[i][j] = expf(asmix * h[16 + i * 4 + j] + stream_mixing[i * 4 + j]);

    for (int it = 0; it < 20; it++) {
#pragma unroll
        for (int i = 0; i < 4; i++) {
            const float inv = 1.0f / (p[i][0] + p[i][1] + p[i][2] + p[i][3]);
#pragma unroll
            for (int j = 0; j < 4; j++) p[i][j] *= inv;
        }
#pragma unroll
        for (int j = 0; j < 4; j++) {
            const float inv = 1.0f / (p[0][j] + p[1][j] + p[2][j] + p[3][j]);
#pragma unroll
            for (int i = 0; i < 4; i++) p[i][j] *= inv;
        }
    }
#pragma unroll
    for (int n = 0; n < 4; n++)
#pragma unroll
        for (int j = 0; j < 4; j++)
            g_C[b * 16 + n * 4 + j] =
                wo[n][0] * riT[0][j] + wo[n][1] * riT[1][j] + p[n][j];
}

// ---------------------------------------------------------------------------
// K3: out[b, n*1024+d] = sum_j C_b[n][j] * x[b, j*1024+d]. One CTA per row,
// each thread owns one float4 column slot. Pure stream: 256MB in + 256MB out.
// ---------------------------------------------------------------------------
__global__ __launch_bounds__(256)
void k3_out(const float* __restrict__ x, float* __restrict__ out) {
    const int b = blockIdx.x;
    __shared__ float Cs[16];
    if (threadIdx.x < 16) Cs[threadIdx.x] = g_C[b * 16 + threadIdx.x];
    __syncthreads();

    const int c = threadIdx.x;
    const float4* xb = (const float4*)(x + (size_t)b * K_DIM);
    float4* ob = (float4*)(out + (size_t)b * K_DIM);

    float4 xv[4];
#pragma unroll
    for (int j = 0; j < 4; j++) xv[j] = xb[j * 256 + c];

#pragma unroll
    for (int n = 0; n < 4; n++) {
        const float c0 = Cs[n * 4 + 0], c1 = Cs[n * 4 + 1],
                    c2 = Cs[n * 4 + 2], c3 = Cs[n * 4 + 3];
        float4 o;
        o.x = c0 * xv[0].x + c1 * xv[1].x + c2 * xv[2].x + c3 * xv[3].x;
        o.y = c0 * xv[0].y + c1 * xv[1].y + c2 * xv[2].y + c3 * xv[3].y;
        o.z = c0 * xv[0].z + c1 * xv[1].z + c2 * xv[2].z + c3 * xv[3].z;
        o.w = c0 * xv[0].w + c1 * xv[1].w + c2 * xv[2].w + c3 * xv[3].w;
        ob[n * 256 + c] = o;
    }
}

extern "C" void kernel_launch(void* const* d_in, const int* in_sizes, int n_in,
                              void* d_out, int out_size) {
    const float* x         = (const float*)d_in[0];
    const float* read_in   = (const float*)d_in[1];
    const float* a_ri      = (const float*)d_in[2];
    const float* write_out = (const float*)d_in[3];
    const float* a_wo      = (const float*)d_in[4];
    const float* smix      = (const float*)d_in[5];
    const float* a_sm      = (const float*)d_in[6];
    const float* Wri       = (const float*)d_in[7];
    const float* Wwo       = (const float*)d_in[8];
    const float* Wsm       = (const float*)d_in[9];
    float* out = (float*)d_out;

    k1_dots<<<B_TOTAL / 16, 512>>>(x, Wri, Wwo, Wsm);
    k2_gates<<<B_TOTAL / 256, 256>>>(read_in, a_ri, write_out, a_wo, smix, a_sm);
    k3_out<<<B_TOTAL, 256>>>(x, out);
}

// round 2
// speedup vs baseline: 1.3845x; 1.3845x over previous
#include <cuda_runtime.h>
#include <cstdint>

#define B_TOTAL 16384
#define K_DIM   4096
#define NDOTS   32
#define F_EPS   1.1920929e-07f
#define STAGES  3

// smem layout (floats):
//   xs: STAGES * 16 * 128   = 6144
//   ws: XS_TOT + STAGES*32*128 = 12288
//   Hs: 16*32, SSs: 16, Cs: 16*16
#define XS_TOT (STAGES * 16 * 128)
#define WS_TOT (STAGES * 32 * 128)
#define SMEM_FLOATS (XS_TOT + WS_TOT + 16 * 32 + 16 + 16 * 16)

__device__ __forceinline__ void ffma2(unsigned long long &acc,
                                      unsigned long long a,
                                      unsigned long long b) {
    asm("fma.rn.f32x2 %0, %1, %2, %0;" : "+l"(acc) : "l"(a), "l"(b));
}
__device__ __forceinline__ float hsum2(unsigned long long v) {
    return __uint_as_float((unsigned)(v & 0xffffffffull)) +
           __uint_as_float((unsigned)(v >> 32));
}
__device__ __forceinline__ void cp_async16(uint32_t saddr, const void* g) {
    asm volatile("cp.async.cg.shared.global [%0], [%1], 16;\n" :: "r"(saddr), "l"(g));
}
__device__ __forceinline__ void cp_commit() {
    asm volatile("cp.async.commit_group;\n");
}
template <int N>
__device__ __forceinline__ void cp_wait() {
    asm volatile("cp.async.wait_group %0;\n" :: "n"(N));
}

// ---------------------------------------------------------------------------
// Fused kernel. Grid 1024, block 512. CTA owns 16 rows.
// Phase A: 32 dots/row + sumsq, cp.async 3-stage pipelined tiles (k chunks of 128).
// Phase B: 16 threads -> sigmoids + 20-iter Sinkhorn -> 4x4 C per row (smem).
// Phase C: warp-per-row out = C @ x (x re-read, mostly L2-resident).
// ---------------------------------------------------------------------------
__global__ __launch_bounds__(512, 1)
void mhc_fused(const float* __restrict__ x,
               const float* __restrict__ Wri,
               const float* __restrict__ Wwo,
               const float* __restrict__ Wsm,
               const float* __restrict__ read_in,  const float* __restrict__ a_ri,
               const float* __restrict__ write_out, const float* __restrict__ a_wo,
               const float* __restrict__ stream_mixing, const float* __restrict__ a_sm,
               float* __restrict__ out) {
    extern __shared__ float sm[];
    float* xs  = sm;                    // [STAGES][16][128]
    float* ws  = sm + XS_TOT;           // [STAGES][32][128]
    float* Hs  = sm + XS_TOT + WS_TOT;  // [16][32]
    float* SSs = Hs + 16 * 32;          // [16]
    float* Cs  = SSs + 16;              // [16][16]

    const int tid  = threadIdx.x;
    const int warp = tid >> 5;
    const int lane = tid & 31;
    const int rg   = warp & 3;   // row group (4 rows)
    const int dg   = warp >> 2;  // dot group (8 dots)
    const int row0 = blockIdx.x * 16;

    // ---- phase A: pipelined dots ----
    const int lrow = tid >> 5;   // x-load row (0..15), one warp per row
    const int lkq  = tid & 31;
    const float* xsrc = x + (size_t)(row0 + lrow) * K_DIM + lkq * 4;

    // W row pointer for this thread's two fetch slots (fixed across tiles)
    const float* wsrc[2];
    int wdst[2];
#pragma unroll
    for (int l = 0; l < 2; l++) {
        const int fidx = tid + l * 512;
        const int d  = fidx >> 5;
        const int kq = fidx & 31;
        const float* wrow = (d < 8)  ? (Wri + d * K_DIM)
                          : (d < 16) ? (Wwo + (d - 8) * K_DIM)
                                     : (Wsm + (d - 16) * K_DIM);
        wsrc[l] = wrow + kq * 4;
        wdst[l] = d * 128 + kq * 4;
    }
    const int xdst = lrow * 128 + lkq * 4;

    auto fetch = [&](int t) {
        const int st = t % STAGES;
        const int k0 = t * 128;
        cp_async16((uint32_t)__cvta_generic_to_shared(&xs[st * 2048 + xdst]),
                   xsrc + k0);
#pragma unroll
        for (int l = 0; l < 2; l++)
            cp_async16((uint32_t)__cvta_generic_to_shared(&ws[st * 4096 + wdst[l]]),
                       wsrc[l] + k0);
        cp_commit();
    };

    fetch(0);
    fetch(1);

    unsigned long long acc[4][8];
#pragma unroll
    for (int i = 0; i < 4; i++)
#pragma unroll
        for (int j = 0; j < 8; j++) acc[i][j] = 0ull;
    unsigned long long ss[4] = {0ull, 0ull, 0ull, 0ull};

    for (int t = 0; t < 32; t++) {
        cp_wait<STAGES - 2>();   // tile t landed
        __syncthreads();         // visible to all; stage (t+2)%3 free for reuse
        if (t + 2 < 32) fetch(t + 2);

        const int st = t % STAGES;
        const float* xt = xs + st * 2048;
        const float* wt = ws + st * 4096;

        unsigned long long xa[4], xb[4];
#pragma unroll
        for (int i = 0; i < 4; i++) {
            const ulonglong2 v = *(const ulonglong2*)(xt + (rg * 4 + i) * 128 + lane * 4);
            xa[i] = v.x; xb[i] = v.y;
        }
        if (dg == 0) {
#pragma unroll
            for (int i = 0; i < 4; i++) {
                ffma2(ss[i], xa[i], xa[i]);
                ffma2(ss[i], xb[i], xb[i]);
            }
        }
#pragma unroll
        for (int j = 0; j < 8; j++) {
            const ulonglong2 w = *(const ulonglong2*)(wt + (dg * 8 + j) * 128 + lane * 4);
#pragma unroll
            for (int i = 0; i < 4; i++) {
                ffma2(acc[i][j], xa[i], w.x);
                ffma2(acc[i][j], xb[i], w.y);
            }
        }
        __syncthreads();
    }

    // cross-lane reduction into smem
#pragma unroll
    for (int i = 0; i < 4; i++) {
#pragma unroll
        for (int j = 0; j < 8; j++) {
            float v = hsum2(acc[i][j]);
#pragma unroll
            for (int off = 16; off; off >>= 1)
                v += __shfl_xor_sync(0xffffffffu, v, off);
            if (lane == i * 8 + j)
                Hs[(rg * 4 + i) * 32 + dg * 8 + j] = v;
        }
    }
    if (dg == 0) {
#pragma unroll
        for (int i = 0; i < 4; i++) {
            float v = hsum2(ss[i]);
#pragma unroll
            for (int off = 16; off; off >>= 1)
                v += __shfl_xor_sync(0xffffffffu, v, off);
            if (lane == 0) SSs[rg * 4 + i] = v;
        }
    }
    __syncthreads();

    // ---- phase B: gates + Sinkhorn (16 threads, one per row) ----
    if (tid < 16) {
        const int r = tid;
        const float s = rsqrtf(SSs[r] * (1.0f / (float)K_DIM) + F_EPS);
        float h[32];
#pragma unroll
        for (int d = 0; d < 32; d++) h[d] = Hs[r * 32 + d] * s;

        const float ari = a_ri[0], awo = a_wo[0], asmix = a_sm[0];
        float riT[2][4], wo[4][2], p[4][4];
#pragma unroll
        for (int n = 0; n < 4; n++)
#pragma unroll
            for (int m = 0; m < 2; m++) {
                const float hri = ari * h[n * 2 + m] + read_in[n * 2 + m];
                riT[m][n] = 1.0f / (1.0f + expf(-hri));
                const float hwo = awo * h[8 + n * 2 + m] + write_out[n * 2 + m];
                wo[n][m] = 2.0f / (1.0f + expf(-hwo));
            }
#pragma unroll
        for (int i = 0; i < 4; i++)
#pragma unroll
            for (int j = 0; j < 4; j++)
                p[i][j] = expf(asmix * h[16 + i * 4 + j] + stream_mixing[i * 4 + j]);

        for (int it = 0; it < 20; it++) {
#pragma unroll
            for (int i = 0; i < 4; i++) {
                const float inv = 1.0f / (p[i][0] + p[i][1] + p[i][2] + p[i][3]);
#pragma unroll
                for (int j = 0; j < 4; j++) p[i][j] *= inv;
            }
#pragma unroll
            for (int j = 0; j < 4; j++) {
                const float inv = 1.0f / (p[0][j] + p[1][j] + p[2][j] + p[3][j]);
#pragma unroll
                for (int i = 0; i < 4; i++) p[i][j] *= inv;
            }
        }
#pragma unroll
        for (int n = 0; n < 4; n++)
#pragma unroll
            for (int j = 0; j < 4; j++)
                Cs[r * 16 + n * 4 + j] =
                    wo[n][0] * riT[0][j] + wo[n][1] * riT[1][j] + p[n][j];
    }
    __syncthreads();

    // ---- phase C: out = C @ x, warp per row (x mostly L2-resident) ----
    {
        const int r = warp;           // 16 warps = 16 rows
        float c[4][4];
#pragma unroll
        for (int n = 0; n < 4; n++)
#pragma unroll
            for (int j = 0; j < 4; j++) c[n][j] = Cs[r * 16 + n * 4 + j];

        const float4* xr = (const float4*)(x + (size_t)(row0 + r) * K_DIM);
        float4* orow = (float4*)(out + (size_t)(row0 + r) * K_DIM);

#pragma unroll
        for (int pch = 0; pch < 8; pch++) {
            const int col = pch * 32 + lane;
            float4 xv[4];
#pragma unroll
            for (int j = 0; j < 4; j++) xv[j] = xr[j * 256 + col];
#pragma unroll
            for (int n = 0; n < 4; n++) {
                float4 o;
                o.x = c[n][0] * xv[0].x + c[n][1] * xv[1].x + c[n][2] * xv[2].x + c[n][3] * xv[3].x;
                o.y = c[n][0] * xv[0].y + c[n][1] * xv[1].y + c[n][2] * xv[2].y + c[n][3] * xv[3].y;
                o.z = c[n][0] * xv[0].z + c[n][1] * xv[1].z + c[n][2] * xv[2].z + c[n][3] * xv[3].z;
                o.w = c[n][0] * xv[0].w + c[n][1] * xv[1].w + c[n][2] * xv[2].w + c[n][3] * xv[3].w;
                orow[n * 256 + col] = o;
            }
        }
    }
}

extern "C" void kernel_launch(void* const* d_in, const int* in_sizes, int n_in,
                              void* d_out, int out_size) {
    const float* x         = (const float*)d_in[0];
    const float* read_in   = (const float*)d_in[1];
    const float* a_ri      = (const float*)d_in[2];
    const float* write_out = (const float*)d_in[3];
    const float* a_wo      = (const float*)d_in[4];
    const float* smix      = (const float*)d_in[5];
    const float* a_sm      = (const float*)d_in[6];
    const float* Wri       = (const float*)d_in[7];
    const float* Wwo       = (const float*)d_in[8];
    const float* Wsm       = (const float*)d_in[9];
    float* out = (float*)d_out;

    const int smem_bytes = SMEM_FLOATS * sizeof(float);
    cudaFuncSetAttribute(mhc_fused, cudaFuncAttributeMaxDynamicSharedMemorySize,
                         smem_bytes);
    mhc_fused<<<B_TOTAL / 16, 512, smem_bytes>>>(
        x, Wri, Wwo, Wsm, read_in, a_ri, write_out, a_wo, smix, a_sm, out);
}

// round 3
// speedup vs baseline: 1.5092x; 1.0901x over previous
#include <cuda_runtime.h>
#include <cstdint>

#define B_TOTAL 16384
#define K_DIM   4096
#define F_EPS   1.1920929e-07f

#define KT      512                 // k-columns per stage
#define NTILES  (K_DIM / KT)        // 8
#define STAGES  2
#define XS_FLOATS (16 * KT)         // 8192
#define WS_FLOATS (32 * KT)         // 16384
#define STAGE_FLOATS (XS_FLOATS + WS_FLOATS)   // 24576
#define SMEM_FLOATS (STAGES * STAGE_FLOATS + 16 * 32 + 16 + 16 * 16)

__device__ __forceinline__ void ffma2(unsigned long long &acc,
                                      unsigned long long a,
                                      unsigned long long b) {
    asm("fma.rn.f32x2 %0, %1, %2, %0;" : "+l"(acc) : "l"(a), "l"(b));
}
__device__ __forceinline__ float hsum2(unsigned long long v) {
    return __uint_as_float((unsigned)(v & 0xffffffffull)) +
           __uint_as_float((unsigned)(v >> 32));
}
__device__ __forceinline__ void cp_async16(uint32_t saddr, const void* g) {
    asm volatile("cp.async.cg.shared.global [%0], [%1], 16;\n" :: "r"(saddr), "l"(g));
}
__device__ __forceinline__ void cp_commit() {
    asm volatile("cp.async.commit_group;\n");
}
template <int N>
__device__ __forceinline__ void cp_wait() {
    asm volatile("cp.async.wait_group %0;\n" :: "n"(N));
}

// ---------------------------------------------------------------------------
// Fused kernel. Grid 1024, block 512. CTA owns 16 rows.
// Phase A: 32 dots/row + sumsq. 8 tiles of 512 k, double-buffered cp.async,
//          ONE __syncthreads per tile. Warp tile: 4 rows x 8 dots, lane = k-quad.
// Phase B: 16 threads -> sigmoids + 20-iter Sinkhorn -> 4x4 C per row.
// Phase C: warp-per-row out = C @ x.
// ---------------------------------------------------------------------------
__global__ __launch_bounds__(512, 1)
void mhc_fused(const float* __restrict__ x,
               const float* __restrict__ Wri,
               const float* __restrict__ Wwo,
               const float* __restrict__ Wsm,
               const float* __restrict__ read_in,  const float* __restrict__ a_ri,
               const float* __restrict__ write_out, const float* __restrict__ a_wo,
               const float* __restrict__ stream_mixing, const float* __restrict__ a_sm,
               float* __restrict__ out) {
    extern __shared__ float sm[];
    float* Hs  = sm + STAGES * STAGE_FLOATS;  // [16][32]
    float* SSs = Hs + 16 * 32;                // [16]
    float* Cs  = SSs + 16;                    // [16][16]

    const int tid  = threadIdx.x;
    const int warp = tid >> 5;
    const int lane = tid & 31;
    const int rg   = warp & 3;   // row group (4 rows)
    const int dg   = warp >> 2;  // dot group (8 dots)
    const int row0 = blockIdx.x * 16;

    // ---- phase A fetch: 48KB*? -> per tile: 16x512 x-floats + 32x512 w-floats
    //      = 6144 float4 / 512 threads = 12 cp.async per thread per tile.
    auto fetch = [&](int t) {
        const int st = t & 1;
        const int k0 = t * KT;
        float* stage = sm + st * STAGE_FLOATS;
#pragma unroll
        for (int i = 0; i < 12; i++) {
            const int f = tid + i * 512;
            if (f < 16 * (KT / 4)) {                   // x part
                const int row = f / (KT / 4);
                const int kq  = f % (KT / 4);
                cp_async16((uint32_t)__cvta_generic_to_shared(
                               stage + row * KT + kq * 4),
                           x + (size_t)(row0 + row) * K_DIM + k0 + kq * 4);
            } else {                                    // w part
                const int f2 = f - 16 * (KT / 4);
                const int d  = f2 / (KT / 4);
                const int kq = f2 % (KT / 4);
                const float* wrow = (d < 8)  ? (Wri + d * K_DIM)
                                  : (d < 16) ? (Wwo + (d - 8) * K_DIM)
                                             : (Wsm + (d - 16) * K_DIM);
                cp_async16((uint32_t)__cvta_generic_to_shared(
                               stage + XS_FLOATS + d * KT + kq * 4),
                           wrow + k0 + kq * 4);
            }
        }
        cp_commit();
    };

    fetch(0);

    unsigned long long acc[4][8];
#pragma unroll
    for (int i = 0; i < 4; i++)
#pragma unroll
        for (int j = 0; j < 8; j++) acc[i][j] = 0ull;
    unsigned long long ss[4] = {0ull, 0ull, 0ull, 0ull};

    for (int t = 0; t < NTILES; t++) {
        cp_wait<0>();            // this warp's fetch of tile t done
        __syncthreads();         // all warps' fetches done; prev-stage readers done
        if (t + 1 < NTILES) fetch(t + 1);

        const float* stage = sm + (t & 1) * STAGE_FLOATS;
        const float* xt = stage;
        const float* wt = stage + XS_FLOATS;

#pragma unroll
        for (int p = 0; p < KT / 128; p++) {
            const int kb = p * 128 + lane * 4;
            unsigned long long xa[4], xb[4];
#pragma unroll
            for (int i = 0; i < 4; i++) {
                const ulonglong2 v =
                    *(const ulonglong2*)(xt + (rg * 4 + i) * KT + kb);
                xa[i] = v.x; xb[i] = v.y;
            }
            if (dg == 0) {
#pragma unroll
                for (int i = 0; i < 4; i++) {
                    ffma2(ss[i], xa[i], xa[i]);
                    ffma2(ss[i], xb[i], xb[i]);
                }
            }
#pragma unroll
            for (int j = 0; j < 8; j++) {
                const ulonglong2 w =
                    *(const ulonglong2*)(wt + (dg * 8 + j) * KT + kb);
#pragma unroll
                for (int i = 0; i < 4; i++) {
                    ffma2(acc[i][j], xa[i], w.x);
                    ffma2(acc[i][j], xb[i], w.y);
                }
            }
        }
    }
    __syncthreads();   // done reading stages before Hs/Cs phase (stage smem reuse safety)

    // cross-lane reduction into smem
#pragma unroll
    for (int i = 0; i < 4; i++) {
#pragma unroll
        for (int j = 0; j < 8; j++) {
            float v = hsum2(acc[i][j]);
#pragma unroll
            for (int off = 16; off; off >>= 1)
                v += __shfl_xor_sync(0xffffffffu, v, off);
            if (lane == i * 8 + j)
                Hs[(rg * 4 + i) * 32 + dg * 8 + j] = v;
        }
    }
    if (dg == 0) {
#pragma unroll
        for (int i = 0; i < 4; i++) {
            float v = hsum2(ss[i]);
#pragma unroll
            for (int off = 16; off; off >>= 1)
                v += __shfl_xor_sync(0xffffffffu, v, off);
            if (lane == 0) SSs[rg * 4 + i] = v;
        }
    }
    __syncthreads();

    // ---- phase B: gates + Sinkhorn (16 threads, one per row) ----
    if (tid < 16) {
        const int r = tid;
        const float s = rsqrtf(SSs[r] * (1.0f / (float)K_DIM) + F_EPS);
        float h[32];
#pragma unroll
        for (int d = 0; d < 32; d++) h[d] = Hs[r * 32 + d] * s;

        const float ari = a_ri[0], awo = a_wo[0], asmix = a_sm[0];
        float riT[2][4], wo[4][2], p[4][4];
#pragma unroll
        for (int n = 0; n < 4; n++)
#pragma unroll
            for (int m = 0; m < 2; m++) {
                const float hri = ari * h[n * 2 + m] + read_in[n * 2 + m];
                riT[m][n] = 1.0f / (1.0f + expf(-hri));
                const float hwo = awo * h[8 + n * 2 + m] + write_out[n * 2 + m];
                wo[n][m] = 2.0f / (1.0f + expf(-hwo));
            }
#pragma unroll
        for (int i = 0; i < 4; i++)
#pragma unroll
            for (int j = 0; j < 4; j++)
                p[i][j] = expf(asmix * h[16 + i * 4 + j] + stream_mixing[i * 4 + j]);

        for (int it = 0; it < 20; it++) {
#pragma unroll
            for (int i = 0; i < 4; i++) {
                const float inv = 1.0f / (p[i][0] + p[i][1] + p[i][2] + p[i][3]);
#pragma unroll
                for (int j = 0; j < 4; j++) p[i][j] *= inv;
            }
#pragma unroll
            for (int j = 0; j < 4; j++) {
                const float inv = 1.0f / (p[0][j] + p[1][j] + p[2][j] + p[3][j]);
#pragma unroll
                for (int i = 0; i < 4; i++) p[i][j] *= inv;
            }
        }
#pragma unroll
        for (int n = 0; n < 4; n++)
#pragma unroll
            for (int j = 0; j < 4; j++)
                Cs[r * 16 + n * 4 + j] =
                    wo[n][0] * riT[0][j] + wo[n][1] * riT[1][j] + p[n][j];
    }
    __syncthreads();

    // ---- phase C: out = C @ x, warp per row ----
    {
        const int r = warp;           // 16 warps = 16 rows
        float c[4][4];
#pragma unroll
        for (int n = 0; n < 4; n++)
#pragma unroll
            for (int j = 0; j < 4; j++) c[n][j] = Cs[r * 16 + n * 4 + j];

        const float4* xr = (const float4*)(x + (size_t)(row0 + r) * K_DIM);
        float4* orow = (float4*)(out + (size_t)(row0 + r) * K_DIM);

#pragma unroll
        for (int pch = 0; pch < 8; pch++) {
            const int col = pch * 32 + lane;
            float4 xv[4];
#pragma unroll
            for (int j = 0; j < 4; j++) xv[j] = xr[j * 256 + col];
#pragma unroll
            for (int n = 0; n < 4; n++) {
                float4 o;
                o.x = c[n][0] * xv[0].x + c[n][1] * xv[1].x + c[n][2] * xv[2].x + c[n][3] * xv[3].x;
                o.y = c[n][0] * xv[0].y + c[n][1] * xv[1].y + c[n][2] * xv[2].y + c[n][3] * xv[3].y;
                o.z = c[n][0] * xv[0].z + c[n][1] * xv[1].z + c[n][2] * xv[2].z + c[n][3] * xv[3].z;
                o.w = c[n][0] * xv[0].w + c[n][1] * xv[1].w + c[n][2] * xv[2].w + c[n][3] * xv[3].w;
                orow[n * 256 + col] = o;
            }
        }
    }
}

extern "C" void kernel_launch(void* const* d_in, const int* in_sizes, int n_in,
                              void* d_out, int out_size) {
    const float* x         = (const float*)d_in[0];
    const float* read_in   = (const float*)d_in[1];
    const float* a_ri      = (const float*)d_in[2];
    const float* write_out = (const float*)d_in[3];
    const float* a_wo      = (const float*)d_in[4];
    const float* smix      = (const float*)d_in[5];
    const float* a_sm      = (const float*)d_in[6];
    const float* Wri       = (const float*)d_in[7];
    const float* Wwo       = (const float*)d_in[8];
    const float* Wsm       = (const float*)d_in[9];
    float* out = (float*)d_out;

    const int smem_bytes = SMEM_FLOATS * sizeof(float);
    cudaFuncSetAttribute(mhc_fused, cudaFuncAttributeMaxDynamicSharedMemorySize,
                         smem_bytes);
    mhc_fused<<<B_TOTAL / 16, 512, smem_bytes>>>(
        x, Wri, Wwo, Wsm, read_in, a_ri, write_out, a_wo, smix, a_sm, out);
}

// round 4
// speedup vs baseline: 2.6165x; 1.7337x over previous
#include <cuda_runtime.h>
#include <cuda_bf16.h>
#include <cstdint>

#define B_TOTAL  16384
#define K_DIM    4096
#define F_EPS    1.1920929e-07f

#define ROWS_CTA 32
#define KT       128
#define NTILES   (K_DIM / KT)          // 32
// padded smem strides: x rows 136 floats (544B), W rows 136 bf16 (272B)
#define SX_B     544
#define SW_B     272
#define X_STAGE_B (ROWS_CTA * SX_B)    // 17408
#define W_STAGE_B (32 * SW_B)          // 8704
#define STAGE_B   (X_STAGE_B + W_STAGE_B)  // 26112
#define SMEM_B    (2 * STAGE_B)        // 52224 (Hs/SSs alias into stage 0 after k-loop)

__device__ __nv_bfloat16 g_Wb[32 * K_DIM];   // bf16 W, rows: 0-7 ri, 8-15 wo, 16-31 sm
__device__ float g_C[B_TOTAL * 16];          // per-row 4x4 combination matrix

__device__ __forceinline__ void ffma2(unsigned long long &acc,
                                      unsigned long long a,
                                      unsigned long long b) {
    asm("fma.rn.f32x2 %0, %1, %2, %0;" : "+l"(acc) : "l"(a), "l"(b));
}
__device__ __forceinline__ float hsum2(unsigned long long v) {
    return __uint_as_float((unsigned)(v & 0xffffffffull)) +
           __uint_as_float((unsigned)(v >> 32));
}
__device__ __forceinline__ void cp_async16(uint32_t saddr, const void* g) {
    asm volatile("cp.async.cg.shared.global [%0], [%1], 16;\n" :: "r"(saddr), "l"(g));
}
__device__ __forceinline__ void cp_commit() {
    asm volatile("cp.async.commit_group;\n");
}
template <int N>
__device__ __forceinline__ void cp_wait() {
    asm volatile("cp.async.wait_group %0;\n" :: "n"(N));
}
// pack two f32 -> bf16x2 (lo = first arg, hi = second arg)
__device__ __forceinline__ uint32_t cvt_bf2(float lo, float hi) {
    uint32_t r;
    asm("cvt.rn.bf16x2.f32 %0, %1, %2;" : "=r"(r) : "f"(hi), "f"(lo));
    return r;
}
__device__ __forceinline__ void mma_bf16(float &c0, float &c1, float &c2, float &c3,
                                         uint32_t a0, uint32_t a1, uint32_t a2, uint32_t a3,
                                         uint32_t b0, uint32_t b1) {
    asm volatile(
        "mma.sync.aligned.m16n8k16.row.col.f32.bf16.bf16.f32 "
        "{%0,%1,%2,%3}, {%4,%5,%6,%7}, {%8,%9}, {%0,%1,%2,%3};"
        : "+f"(c0), "+f"(c1), "+f"(c2), "+f"(c3)
        : "r"(a0), "r"(a1), "r"(a2), "r"(a3), "r"(b0), "r"(b1));
}

// ---------------------------------------------------------------------------
// prepass: W fp32 -> bf16 into g_Wb
// ---------------------------------------------------------------------------
__global__ __launch_bounds__(256)
void wconv(const float* __restrict__ Wri, const float* __restrict__ Wwo,
           const float* __restrict__ Wsm) {
    const int base = (blockIdx.x * 256 + threadIdx.x) * 4;   // grid 128 -> 131072 elems
    const int d = base / K_DIM;
    const int k = base % K_DIM;
    const float* wrow = (d < 8)  ? (Wri + d * K_DIM)
                      : (d < 16) ? (Wwo + (d - 8) * K_DIM)
                                 : (Wsm + (d - 16) * K_DIM);
    const float4 v = *(const float4*)(wrow + k);
    uint32_t p0 = cvt_bf2(v.x, v.y);
    uint32_t p1 = cvt_bf2(v.z, v.w);
    *(uint2*)(&g_Wb[d * K_DIM + k]) = make_uint2(p0, p1);
}

// ---------------------------------------------------------------------------
// K1: dots via bf16 mma + sumsq + gates/Sinkhorn -> g_C.
// Grid 512, block 128 (4 warps). CTA = 32 rows. Warp tile 16 rows x 16 dots.
// ---------------------------------------------------------------------------
__global__ __launch_bounds__(128, 4)
void mhc_dots(const float* __restrict__ x,
              const float* __restrict__ read_in,  const float* __restrict__ a_ri,
              const float* __restrict__ write_out, const float* __restrict__ a_wo,
              const float* __restrict__ stream_mixing, const float* __restrict__ a_sm) {
    extern __shared__ char smc[];
    const int tid  = threadIdx.x;
    const int warp = tid >> 5;
    const int lane = tid & 31;
    const int row0 = blockIdx.x * ROWS_CTA;
    const int rb   = warp & 1;    // row block (16 rows)
    const int db   = warp >> 1;   // dot block (16 dots)

    const uint32_t sbase = (uint32_t)__cvta_generic_to_shared(smc);

    // ---- fetch: per tile 1024 x-float4 + 512 W-16B-chunks = 1536 / 128 thr = 12
    auto fetch = [&](int t) {
        const uint32_t st = sbase + (t & 1) * STAGE_B;
        const int k0 = t * KT;
#pragma unroll
        for (int i = 0; i < 12; i++) {
            const int f = tid + i * 128;
            if (f < 1024) {                        // x: 32 rows x 32 quads
                const int row = f >> 5, kq = f & 31;
                cp_async16(st + row * SX_B + kq * 16,
                           x + (size_t)(row0 + row) * K_DIM + k0 + kq * 4);
            } else {                               // W: 32 rows x 16 chunks of 8 bf16
                const int f2 = f - 1024;
                const int d = f2 >> 4, kc = f2 & 15;
                cp_async16(st + X_STAGE_B + d * SW_B + kc * 16,
                           g_Wb + d * K_DIM + k0 + kc * 8);
            }
        }
        cp_commit();
    };

    fetch(0);

    float c[2][4];
#pragma unroll
    for (int n = 0; n < 2; n++)
#pragma unroll
        for (int j = 0; j < 4; j++) c[n][j] = 0.0f;
    unsigned long long ss[8];
#pragma unroll
    for (int i = 0; i < 8; i++) ss[i] = 0ull;

    const int g = lane >> 2;      // 0..7
    const int cc = lane & 3;      // 0..3

    for (int t = 0; t < NTILES; t++) {
        cp_wait<0>();
        __syncthreads();
        if (t + 1 < NTILES) fetch(t + 1);

        const char* stage = smc + (t & 1) * STAGE_B;
        const char* xs = stage;
        const char* ws = stage + X_STAGE_B;

        // sumsq: warp owns rows warp*8..+7, lane owns 4 cols
#pragma unroll
        for (int rr = 0; rr < 8; rr++) {
            const ulonglong2 u =
                *(const ulonglong2*)(xs + (warp * 8 + rr) * SX_B + lane * 16);
            ffma2(ss[rr], u.x, u.x);
            ffma2(ss[rr], u.y, u.y);
        }

        // mma over 8 k16-steps
#pragma unroll
        for (int s = 0; s < 8; s++) {
            const int kb = s * 16;
            const char* arow = xs + (rb * 16 + g) * SX_B + (kb + cc * 2) * 4;
            const float2 fa0 = *(const float2*)(arow);
            const float2 fa1 = *(const float2*)(arow + 8 * SX_B);
            const float2 fa2 = *(const float2*)(arow + 32);
            const float2 fa3 = *(const float2*)(arow + 8 * SX_B + 32);
            const uint32_t a0 = cvt_bf2(fa0.x, fa0.y);
            const uint32_t a1 = cvt_bf2(fa1.x, fa1.y);
            const uint32_t a2 = cvt_bf2(fa2.x, fa2.y);
            const uint32_t a3 = cvt_bf2(fa3.x, fa3.y);
#pragma unroll
            for (int ng = 0; ng < 2; ng++) {
                const char* brow =
                    ws + (db * 16 + ng * 8 + g) * SW_B + (kb + cc * 2) * 2;
                const uint32_t b0 = *(const uint32_t*)(brow);
                const uint32_t b1 = *(const uint32_t*)(brow + 16);
                mma_bf16(c[ng][0], c[ng][1], c[ng][2], c[ng][3],
                         a0, a1, a2, a3, b0, b1);
            }
        }
    }
    __syncthreads();   // all reads of stage smem done -> safe to alias Hs/SSs

    float* Hs  = (float*)smc;          // [32][32]
    float* SSs = (float*)(smc + 4096); // [32]

    // write H from accumulators (already k-reduced by mma)
#pragma unroll
    for (int ng = 0; ng < 2; ng++) {
        const int d0 = db * 16 + ng * 8 + cc * 2;
        const int r0l = rb * 16 + g;
        Hs[r0l * 32 + d0]           = c[ng][0];
        Hs[r0l * 32 + d0 + 1]       = c[ng][1];
        Hs[(r0l + 8) * 32 + d0]     = c[ng][2];
        Hs[(r0l + 8) * 32 + d0 + 1] = c[ng][3];
    }
    // sumsq butterfly
#pragma unroll
    for (int rr = 0; rr < 8; rr++) {
        float v = hsum2(ss[rr]);
#pragma unroll
        for (int off = 16; off; off >>= 1)
            v += __shfl_xor_sync(0xffffffffu, v, off);
        if (lane == rr) SSs[warp * 8 + rr] = v;
    }
    __syncthreads();

    // gates + Sinkhorn: one thread per row
    if (tid < 32) {
        const int r = tid;
        const float s = rsqrtf(SSs[r] * (1.0f / (float)K_DIM) + F_EPS);
        float h[32];
#pragma unroll
        for (int d = 0; d < 32; d++) h[d] = Hs[r * 32 + d] * s;

        const float ari = a_ri[0], awo = a_wo[0], asmix = a_sm[0];
        float riT[2][4], wo[4][2], p[4][4];
#pragma unroll
        for (int n = 0; n < 4; n++)
#pragma unroll
            for (int m = 0; m < 2; m++) {
                const float hri = ari * h[n * 2 + m] + read_in[n * 2 + m];
                riT[m][n] = 1.0f / (1.0f + expf(-hri));
                const float hwo = awo * h[8 + n * 2 + m] + write_out[n * 2 + m];
                wo[n][m] = 2.0f / (1.0f + expf(-hwo));
            }
#pragma unroll
        for (int i = 0; i < 4; i++)
#pragma unroll
            for (int j = 0; j < 4; j++)
                p[i][j] = expf(asmix * h[16 + i * 4 + j] + stream_mixing[i * 4 + j]);

        for (int it = 0; it < 20; it++) {
#pragma unroll
            for (int i = 0; i < 4; i++) {
                const float inv = 1.0f / (p[i][0] + p[i][1] + p[i][2] + p[i][3]);
#pragma unroll
                for (int j = 0; j < 4; j++) p[i][j] *= inv;
            }
#pragma unroll
            for (int j = 0; j < 4; j++) {
                const float inv = 1.0f / (p[0][j] + p[1][j] + p[2][j] + p[3][j]);
#pragma unroll
                for (int i = 0; i < 4; i++) p[i][j] *= inv;
            }
        }
#pragma unroll
        for (int n = 0; n < 4; n++)
#pragma unroll
            for (int j = 0; j < 4; j++)
                g_C[(size_t)(row0 + r) * 16 + n * 4 + j] =
                    wo[n][0] * riT[0][j] + wo[n][1] * riT[1][j] + p[n][j];
    }
}

// ---------------------------------------------------------------------------
// K2: out[b, n*1024+d] = sum_j C_b[n][j] * x[b, j*1024+d]. One CTA per row.
// ---------------------------------------------------------------------------
__global__ __launch_bounds__(256)
void k3_out(const float* __restrict__ x, float* __restrict__ out) {
    const int b = blockIdx.x;
    __shared__ float Cs[16];
    if (threadIdx.x < 16) Cs[threadIdx.x] = g_C[b * 16 + threadIdx.x];
    __syncthreads();

    const int ci = threadIdx.x;
    const float4* xb = (const float4*)(x + (size_t)b * K_DIM);
    float4* ob = (float4*)(out + (size_t)b * K_DIM);

    float4 xv[4];
#pragma unroll
    for (int j = 0; j < 4; j++) xv[j] = xb[j * 256 + ci];

#pragma unroll
    for (int n = 0; n < 4; n++) {
        const float c0 = Cs[n * 4 + 0], c1 = Cs[n * 4 + 1],
                    c2 = Cs[n * 4 + 2], c3 = Cs[n * 4 + 3];
        float4 o;
        o.x = c0 * xv[0].x + c1 * xv[1].x + c2 * xv[2].x + c3 * xv[3].x;
        o.y = c0 * xv[0].y + c1 * xv[1].y + c2 * xv[2].y + c3 * xv[3].y;
        o.z = c0 * xv[0].z + c1 * xv[1].z + c2 * xv[2].z + c3 * xv[3].z;
        o.w = c0 * xv[0].w + c1 * xv[1].w + c2 * xv[2].w + c3 * xv[3].w;
        ob[n * 256 + ci] = o;
    }
}

extern "C" void kernel_launch(void* const* d_in, const int* in_sizes, int n_in,
                              void* d_out, int out_size) {
    const float* x         = (const float*)d_in[0];
    const float* read_in   = (const float*)d_in[1];
    const float* a_ri      = (const float*)d_in[2];
    const float* write_out = (const float*)d_in[3];
    const float* a_wo      = (const float*)d_in[4];
    const float* smix      = (const float*)d_in[5];
    const float* a_sm      = (const float*)d_in[6];
    const float* Wri       = (const float*)d_in[7];
    const float* Wwo       = (const float*)d_in[8];
    const float* Wsm       = (const float*)d_in[9];
    float* out = (float*)d_out;

    wconv<<<128, 256>>>(Wri, Wwo, Wsm);

    cudaFuncSetAttribute(mhc_dots, cudaFuncAttributeMaxDynamicSharedMemorySize,
                         SMEM_B);
    mhc_dots<<<B_TOTAL / ROWS_CTA, 128, SMEM_B>>>(
        x, read_in, a_ri, write_out, a_wo, smix, a_sm);

    k3_out<<<B_TOTAL, 256>>>(x, out);
}

// round 5
// speedup vs baseline: 2.6889x; 1.0277x over previous
#include <cuda_runtime.h>
#include <cuda_bf16.h>
#include <cstdint>

#define B_TOTAL  16384
#define K_DIM    4096
#define F_EPS    1.1920929e-07f

#define ROWS_CTA 64
#define KT       128
#define NTILES   (K_DIM / KT)          // 32
// padded smem strides: x rows 136 floats (544B), W rows 136 bf16 (272B)
#define SX_B     544
#define SW_B     272
#define X_STAGE_B (ROWS_CTA * SX_B)    // 34816
#define W_STAGE_B (32 * SW_B)          // 8704
#define STAGE_B   (X_STAGE_B + W_STAGE_B)  // 43520
#define SMEM_B    (2 * STAGE_B)        // 87040 (Hs/SSs alias into stage 0 after k-loop)

__device__ __nv_bfloat16 g_Wb[32 * K_DIM];   // bf16 W, rows: 0-7 ri, 8-15 wo, 16-31 sm
__device__ float g_C[B_TOTAL * 16];          // per-row 4x4 combination matrix

__device__ __forceinline__ void ffma2(unsigned long long &acc,
                                      unsigned long long a,
                                      unsigned long long b) {
    asm("fma.rn.f32x2 %0, %1, %2, %0;" : "+l"(acc) : "l"(a), "l"(b));
}
__device__ __forceinline__ float hsum2(unsigned long long v) {
    return __uint_as_float((unsigned)(v & 0xffffffffull)) +
           __uint_as_float((unsigned)(v >> 32));
}
__device__ __forceinline__ void cp_async16(uint32_t saddr, const void* g) {
    asm volatile("cp.async.cg.shared.global [%0], [%1], 16;\n" :: "r"(saddr), "l"(g));
}
__device__ __forceinline__ void cp_commit() {
    asm volatile("cp.async.commit_group;\n");
}
template <int N>
__device__ __forceinline__ void cp_wait() {
    asm volatile("cp.async.wait_group %0;\n" :: "n"(N));
}
// pack two f32 -> bf16x2 (lo = first arg, hi = second arg)
__device__ __forceinline__ uint32_t cvt_bf2(float lo, float hi) {
    uint32_t r;
    asm("cvt.rn.bf16x2.f32 %0, %1, %2;" : "=r"(r) : "f"(hi), "f"(lo));
    return r;
}
__device__ __forceinline__ void mma_bf16(float &c0, float &c1, float &c2, float &c3,
                                         uint32_t a0, uint32_t a1, uint32_t a2, uint32_t a3,
                                         uint32_t b0, uint32_t b1) {
    asm volatile(
        "mma.sync.aligned.m16n8k16.row.col.f32.bf16.bf16.f32 "
        "{%0,%1,%2,%3}, {%4,%5,%6,%7}, {%8,%9}, {%0,%1,%2,%3};"
        : "+f"(c0), "+f"(c1), "+f"(c2), "+f"(c3)
        : "r"(a0), "r"(a1), "r"(a2), "r"(a3), "r"(b0), "r"(b1));
}

// ---------------------------------------------------------------------------
// prepass: W fp32 -> bf16 into g_Wb
// ---------------------------------------------------------------------------
__global__ __launch_bounds__(256)
void wconv(const float* __restrict__ Wri, const float* __restrict__ Wwo,
           const float* __restrict__ Wsm) {
    const int base = (blockIdx.x * 256 + threadIdx.x) * 4;   // grid 128 -> 131072 elems
    const int d = base / K_DIM;
    const int k = base % K_DIM;
    const float* wrow = (d < 8)  ? (Wri + d * K_DIM)
                      : (d < 16) ? (Wwo + (d - 8) * K_DIM)
                                 : (Wsm + (d - 16) * K_DIM);
    const float4 v = *(const float4*)(wrow + k);
    uint32_t p0 = cvt_bf2(v.x, v.y);
    uint32_t p1 = cvt_bf2(v.z, v.w);
    *(uint2*)(&g_Wb[d * K_DIM + k]) = make_uint2(p0, p1);
}

// ---------------------------------------------------------------------------
// K1: dots via bf16 mma + fragment-sumsq + gates/Sinkhorn -> g_C.
// Grid 256, block 128 (4 warps). CTA = 64 rows. Warp tile 16 rows x 32 dots:
// every warp owns distinct rows -> x smem tile read exactly once; sumsq
// computed from the A-fragments already in registers.
// ---------------------------------------------------------------------------
__global__ __launch_bounds__(128)
void mhc_dots(const float* __restrict__ x,
              const float* __restrict__ read_in,  const float* __restrict__ a_ri,
              const float* __restrict__ write_out, const float* __restrict__ a_wo,
              const float* __restrict__ stream_mixing, const float* __restrict__ a_sm) {
    extern __shared__ char smc[];
    const int tid  = threadIdx.x;
    const int warp = tid >> 5;          // = row block (16 rows each)
    const int lane = tid & 31;
    const int row0 = blockIdx.x * ROWS_CTA;

    const uint32_t sbase = (uint32_t)__cvta_generic_to_shared(smc);

    // ---- fetch: per tile 2048 x-float4 + 512 W-16B-chunks = 2560 / 128 thr = 20
    auto fetch = [&](int t) {
        const uint32_t st = sbase + (t & 1) * STAGE_B;
        const int k0 = t * KT;
#pragma unroll
        for (int i = 0; i < 20; i++) {
            const int f = tid + i * 128;
            if (f < 2048) {                        // x: 64 rows x 32 quads
                const int row = f >> 5, kq = f & 31;
                cp_async16(st + row * SX_B + kq * 16,
                           x + (size_t)(row0 + row) * K_DIM + k0 + kq * 4);
            } else {                               // W: 32 rows x 16 chunks of 8 bf16
                const int f2 = f - 2048;
                const int d = f2 >> 4, kc = f2 & 15;
                cp_async16(st + X_STAGE_B + d * SW_B + kc * 16,
                           g_Wb + d * K_DIM + k0 + kc * 8);
            }
        }
        cp_commit();
    };

    fetch(0);

    float c[4][4];
#pragma unroll
    for (int n = 0; n < 4; n++)
#pragma unroll
        for (int j = 0; j < 4; j++) c[n][j] = 0.0f;
    unsigned long long ssa = 0ull, ssb = 0ull;   // rows warp*16+g, warp*16+8+g

    const int g  = lane >> 2;     // 0..7
    const int cc = lane & 3;      // 0..3

    for (int t = 0; t < NTILES; t++) {
        cp_wait<0>();
        __syncthreads();
        if (t + 1 < NTILES) fetch(t + 1);

        const char* stage = smc + (t & 1) * STAGE_B;
        const char* xs = stage;
        const char* ws = stage + X_STAGE_B;

#pragma unroll
        for (int s = 0; s < 8; s++) {
            const int kb = s * 16;
            const char* arow = xs + (warp * 16 + g) * SX_B + (kb + cc * 2) * 4;
            const float2 fa0 = *(const float2*)(arow);
            const float2 fa1 = *(const float2*)(arow + 8 * SX_B);
            const float2 fa2 = *(const float2*)(arow + 32);
            const float2 fa3 = *(const float2*)(arow + 8 * SX_B + 32);
            // sumsq from fragments (packed)
            const unsigned long long u0 = *(const unsigned long long*)&fa0;
            const unsigned long long u1 = *(const unsigned long long*)&fa1;
            const unsigned long long u2 = *(const unsigned long long*)&fa2;
            const unsigned long long u3 = *(const unsigned long long*)&fa3;
            ffma2(ssa, u0, u0);
            ffma2(ssa, u2, u2);
            ffma2(ssb, u1, u1);
            ffma2(ssb, u3, u3);

            const uint32_t a0 = cvt_bf2(fa0.x, fa0.y);
            const uint32_t a1 = cvt_bf2(fa1.x, fa1.y);
            const uint32_t a2 = cvt_bf2(fa2.x, fa2.y);
            const uint32_t a3 = cvt_bf2(fa3.x, fa3.y);
#pragma unroll
            for (int ng = 0; ng < 4; ng++) {
                const char* brow = ws + (ng * 8 + g) * SW_B + (kb + cc * 2) * 2;
                const uint32_t b0 = *(const uint32_t*)(brow);
                const uint32_t b1 = *(const uint32_t*)(brow + 16);
                mma_bf16(c[ng][0], c[ng][1], c[ng][2], c[ng][3],
                         a0, a1, a2, a3, b0, b1);
            }
        }
    }
    __syncthreads();   // all reads of stage smem done -> safe to alias Hs/SSs

    float* Hs  = (float*)smc;          // [64][32]
    float* SSs = (float*)(smc + 64 * 32 * 4); // [64]

    // write H from accumulators (already k-reduced by mma)
    {
        const int r0l = warp * 16 + g;
#pragma unroll
        for (int ng = 0; ng < 4; ng++) {
            const int d0 = ng * 8 + cc * 2;
            Hs[r0l * 32 + d0]           = c[ng][0];
            Hs[r0l * 32 + d0 + 1]       = c[ng][1];
            Hs[(r0l + 8) * 32 + d0]     = c[ng][2];
            Hs[(r0l + 8) * 32 + d0 + 1] = c[ng][3];
        }
        // sumsq: reduce across the 4 cc lanes in each quad
        float va = hsum2(ssa), vb = hsum2(ssb);
        va += __shfl_xor_sync(0xffffffffu, va, 1);
        va += __shfl_xor_sync(0xffffffffu, va, 2);
        vb += __shfl_xor_sync(0xffffffffu, vb, 1);
        vb += __shfl_xor_sync(0xffffffffu, vb, 2);
        if (cc == 0) {
            SSs[r0l]     = va;
            SSs[r0l + 8] = vb;
        }
    }
    __syncthreads();

    // gates + Sinkhorn: one thread per row (64 rows, 128 threads)
    if (tid < ROWS_CTA) {
        const int r = tid;
        const float s = rsqrtf(SSs[r] * (1.0f / (float)K_DIM) + F_EPS);
        float h[32];
#pragma unroll
        for (int d = 0; d < 32; d++) h[d] = Hs[r * 32 + d] * s;

        const float ari = a_ri[0], awo = a_wo[0], asmix = a_sm[0];
        float riT[2][4], wo[4][2], p[4][4];
#pragma unroll
        for (int n = 0; n < 4; n++)
#pragma unroll
            for (int m = 0; m < 2; m++) {
                const float hri = ari * h[n * 2 + m] + read_in[n * 2 + m];
                riT[m][n] = 1.0f / (1.0f + expf(-hri));
                const float hwo = awo * h[8 + n * 2 + m] + write_out[n * 2 + m];
                wo[n][m] = 2.0f / (1.0f + expf(-hwo));
            }
#pragma unroll
        for (int i = 0; i < 4; i++)
#pragma unroll
            for (int j = 0; j < 4; j++)
                p[i][j] = expf(asmix * h[16 + i * 4 + j] + stream_mixing[i * 4 + j]);

        for (int it = 0; it < 20; it++) {
#pragma unroll
            for (int i = 0; i < 4; i++) {
                const float inv = 1.0f / (p[i][0] + p[i][1] + p[i][2] + p[i][3]);
#pragma unroll
                for (int j = 0; j < 4; j++) p[i][j] *= inv;
            }
#pragma unroll
            for (int j = 0; j < 4; j++) {
                const float inv = 1.0f / (p[0][j] + p[1][j] + p[2][j] + p[3][j]);
#pragma unroll
                for (int i = 0; i < 4; i++) p[i][j] *= inv;
            }
        }
#pragma unroll
        for (int n = 0; n < 4; n++)
#pragma unroll
            for (int j = 0; j < 4; j++)
                g_C[(size_t)(row0 + r) * 16 + n * 4 + j] =
                    wo[n][0] * riT[0][j] + wo[n][1] * riT[1][j] + p[n][j];
    }
}

// ---------------------------------------------------------------------------
// K2: out[b, n*1024+d] = sum_j C_b[n][j] * x[b, j*1024+d]. One CTA per row.
// Streaming loads/stores (touch-once data; keep L2 clean).
// ---------------------------------------------------------------------------
__global__ __launch_bounds__(256)
void k3_out(const float* __restrict__ x, float* __restrict__ out) {
    const int b = blockIdx.x;
    __shared__ float Cs[16];
    if (threadIdx.x < 16) Cs[threadIdx.x] = g_C[b * 16 + threadIdx.x];
    __syncthreads();

    const int ci = threadIdx.x;
    const float4* xb = (const float4*)(x + (size_t)b * K_DIM);
    float4* ob = (float4*)(out + (size_t)b * K_DIM);

    float4 xv[4];
#pragma unroll
    for (int j = 0; j < 4; j++) xv[j] = __ldcs(&xb[j * 256 + ci]);

#pragma unroll
    for (int n = 0; n < 4; n++) {
        const float c0 = Cs[n * 4 + 0], c1 = Cs[n * 4 + 1],
                    c2 = Cs[n * 4 + 2], c3 = Cs[n * 4 + 3];
        float4 o;
        o.x = c0 * xv[0].x + c1 * xv[1].x + c2 * xv[2].x + c3 * xv[3].x;
        o.y = c0 * xv[0].y + c1 * xv[1].y + c2 * xv[2].y + c3 * xv[3].y;
        o.z = c0 * xv[0].z + c1 * xv[1].z + c2 * xv[2].z + c3 * xv[3].z;
        o.w = c0 * xv[0].w + c1 * xv[1].w + c2 * xv[2].w + c3 * xv[3].w;
        __stcs(&ob[n * 256 + ci], o);
    }
}

extern "C" void kernel_launch(void* const* d_in, const int* in_sizes, int n_in,
                              void* d_out, int out_size) {
    const float* x         = (const float*)d_in[0];
    const float* read_in   = (const float*)d_in[1];
    const float* a_ri      = (const float*)d_in[2];
    const float* write_out = (const float*)d_in[3];
    const float* a_wo      = (const float*)d_in[4];
    const float* smix      = (const float*)d_in[5];
    const float* a_sm      = (const float*)d_in[6];
    const float* Wri       = (const float*)d_in[7];
    const float* Wwo       = (const float*)d_in[8];
    const float* Wsm       = (const float*)d_in[9];
    float* out = (float*)d_out;

    wconv<<<128, 256>>>(Wri, Wwo, Wsm);

    cudaFuncSetAttribute(mhc_dots, cudaFuncAttributeMaxDynamicSharedMemorySize,
                         SMEM_B);
    mhc_dots<<<B_TOTAL / ROWS_CTA, 128, SMEM_B>>>(
        x, read_in, a_ri, write_out, a_wo, smix, a_sm);

    k3_out<<<B_TOTAL, 256>>>(x, out);
}